// round 5
// baseline (speedup 1.0000x reference)
#include <cuda_runtime.h>

#define DIM (1u<<22)
typedef unsigned long long ull;

// Persistent scratch (allowed: __device__ globals, no allocation)
__device__ ull g_bufA[DIM];                 // packed (re,im) amplitudes
__device__ ull g_bufB[DIM];
__device__ __align__(16) ull g_Upk[4*22*8]; // per gate: 8 packed-broadcast consts
__device__ double g_acc[23];                // z[0..21], total at [22]

__device__ __forceinline__ int SWZ(int a){ return a ^ ((a>>4)&15); }

__device__ __forceinline__ ull fma2(ull a, ull b, ull c){
  ull d; asm("fma.rn.f32x2 %0, %1, %2, %3;" : "=l"(d) : "l"(a), "l"(b), "l"(c)); return d;
}
__device__ __forceinline__ ull mul2(ull a, ull b){
  ull d; asm("mul.rn.f32x2 %0, %1, %2;" : "=l"(d) : "l"(a), "l"(b)); return d;
}
__device__ __forceinline__ ull swp(ull a){ return (a>>32)|(a<<32); }
__device__ __forceinline__ ull packf(float lo, float hi){
  return (ull)__float_as_uint(lo) | ((ull)__float_as_uint(hi)<<32);
}

__device__ __forceinline__ float2 cxmul(float2 a, float2 b){
  return make_float2(a.x*b.x - a.y*b.y, a.x*b.y + a.y*b.x);
}

// Apply 2x2 gate on register-bit J over 16 register-resident packed amps.
// Complex update via packed f32x2: res = (u.x,u.x)*a + (-u.y,u.y)*swap(a) + ...
template<int J>
__device__ __forceinline__ void gate16(ull (&r)[16], const ull* __restrict__ Up){
  const ulonglong2 q0 = ((const ulonglong2*)Up)[0];
  const ulonglong2 q1 = ((const ulonglong2*)Up)[1];
  const ulonglong2 q2 = ((const ulonglong2*)Up)[2];
  const ulonglong2 q3 = ((const ulonglong2*)Up)[3];
  const ull c00=q0.x, d00=q0.y, c01=q1.x, d01=q1.y;
  const ull c10=q2.x, d10=q2.y, c11=q3.x, d11=q3.y;
#pragma unroll
  for (int i=0;i<16;i++){
    if ((i & (1<<J)) == 0){
      const int j2 = i | (1<<J);
      const ull a=r[i], b=r[j2], as=swp(a), bs=swp(b);
      r[i]  = fma2(c00,a, fma2(d00,as, fma2(c01,b, mul2(d01,bs))));
      r[j2] = fma2(c10,a, fma2(d10,as, fma2(c11,b, mul2(d11,bs))));
    }
  }
}

// ---------------------------------------------------------------------------
// Prep: zero accumulators, build 88 fused gates U = RZ*RY*RX, packed-broadcast
// ---------------------------------------------------------------------------
__global__ void k_prep(const float* __restrict__ params){
  int i = threadIdx.x;
  if (i < 23) g_acc[i] = 0.0;
  if (i < 88){
    float tx = 0.5f*params[i*3+0];
    float ty = 0.5f*params[i*3+1];
    float tz = 0.5f*params[i*3+2];
    float cx,sx,cy,sy,cz,sz;
    sincosf(tx,&sx,&cx); sincosf(ty,&sy,&cy); sincosf(tz,&sz,&cz);
    // M = RY*RX
    float2 M00 = make_float2( cy*cx,  sy*sx);
    float2 M01 = make_float2(-sy*cx, -cy*sx);
    float2 M10 = make_float2( sy*cx, -cy*sx);
    float2 M11 = make_float2( cy*cx, -sy*sx);
    float2 em = make_float2(cz,-sz), ep = make_float2(cz,sz); // e^{-itz}, e^{+itz}
    float2 U00=cxmul(em,M00), U01=cxmul(em,M01);
    float2 U10=cxmul(ep,M10), U11=cxmul(ep,M11);
    ull* Up = &g_Upk[i*8];
    Up[0]=packf(U00.x,U00.x); Up[1]=packf(-U00.y,U00.y);
    Up[2]=packf(U01.x,U01.x); Up[3]=packf(-U01.y,U01.y);
    Up[4]=packf(U10.x,U10.x); Up[5]=packf(-U10.y,U10.y);
    Up[6]=packf(U11.x,U11.x); Up[7]=packf(-U11.y,U11.y);
  }
}

// ---------------------------------------------------------------------------
// Pass A: gates on global bits 0..11 (qubits 21..10). Tile = 4096 contiguous.
// 2-exchange structure: load in M1 (coalesced), stages M1 -> M2 -> M0,
// store in M0 (coalesced). ALL gate consts staged through smem (low reg
// pressure -> 4 CTAs/SM).
// Layers >= 2 fuse prior layer's CNOT ladder as Gray-code gather in[y^(y>>1)].
//   M0: a=(v<<8)|t                  reg bits = a8..11
//   M1: a=((t>>4)<<8)|(v<<4)|(t&15) reg bits = a4..7
//   M2: a=(t<<4)|v                  reg bits = a0..3
// ---------------------------------------------------------------------------
template<bool FIRST>
__global__ void __launch_bounds__(256,4) k_passA(
    const float* __restrict__ sre, const float* __restrict__ sim,
    int layer, int dir)
{
  __shared__ ull sh[4096];
  __shared__ ull shU[96];   // M1 gates (q17..14), M2 (q21..18), M0 (q13..10)
  const int t = threadIdx.x;
  const unsigned base = (unsigned)blockIdx.x << 12;
  const ull* in  = dir ? g_bufB : g_bufA;
  ull*       out = dir ? g_bufA : g_bufB;
  const ull* Ub = &g_Upk[layer*22*8];
  ull r[16];

  // amp loads first (in flight across the const staging + barrier)
  const unsigned aM1b = (((unsigned)t>>4)<<8) | ((unsigned)t&15);
  if (FIRST){
#pragma unroll
    for (int v=0;v<16;v++){
      unsigned y = base | aM1b | ((unsigned)v<<4);
      r[v] = packf(sre[y], sim[y]);
    }
  } else {
#pragma unroll
    for (int v=0;v<16;v++){
      unsigned y = base | aM1b | ((unsigned)v<<4);
      unsigned x = y ^ (y>>1);          // inverse of CNOT-ladder permutation
      r[v] = in[x];
    }
  }
  if (t < 96){
    const int qmap[12] = {17,16,15,14, 21,20,19,18, 13,12,11,10};
    shU[t] = Ub[qmap[t>>3]*8 + (t&7)];
  }
  __syncthreads();

  // stage M1: reg bit j -> a bit 4+j -> qubit 17-j
  gate16<0>(r, shU + 0);
  gate16<1>(r, shU + 8);
  gate16<2>(r, shU + 16);
  gate16<3>(r, shU + 24);
  // exchange M1 -> M2
#pragma unroll
  for (int v=0;v<16;v++) sh[SWZ(aM1b | (v<<4))] = r[v];
  __syncthreads();
#pragma unroll
  for (int v=0;v<16;v++) r[v] = sh[SWZ((t<<4)|v)];
  // stage M2: reg bit j -> a bit j -> qubit 21-j
  gate16<0>(r, shU + 32);
  gate16<1>(r, shU + 40);
  gate16<2>(r, shU + 48);
  gate16<3>(r, shU + 56);
  // exchange M2 -> M0 (write back to just-read slots: no pre-barrier needed)
#pragma unroll
  for (int v=0;v<16;v++) sh[SWZ((t<<4)|v)] = r[v];
  __syncthreads();
#pragma unroll
  for (int v=0;v<16;v++) r[v] = sh[SWZ((v<<8)|t)];
  // stage M0: reg bit j -> a bit 8+j -> qubit 13-j
  gate16<0>(r, shU + 64);
  gate16<1>(r, shU + 72);
  gate16<2>(r, shU + 80);
  gate16<3>(r, shU + 88);
  // store in M0: coalesced
#pragma unroll
  for (int v=0;v<16;v++) out[base | ((unsigned)v<<8) | (unsigned)t] = r[v];
}

// ---------------------------------------------------------------------------
// Pass B (non-last): gates on global bits 12..21 (qubits 9..0). In-place.
// Tile local a (12b): a bits 0..1 = global bits 0..1 (payload),
// a bit k (k>=2) = global bit 10+k.  g = ((a>>2)<<12)|(blk<<2)|(a&3).
// 2-exchange structure: load M1, stages M1 -> M2 -> M0, store M0.
// ---------------------------------------------------------------------------
__global__ void __launch_bounds__(256,4) k_passB(int layer, int sel)
{
  __shared__ ull sh[4096];
  __shared__ ull shU[80];   // M1 (q7..4), M2 (q9,q8), M0 (q3..0)
  const int t = threadIdx.x;
  const unsigned blk = blockIdx.x;
  ull* buf = sel ? g_bufA : g_bufB;
  const ull* Ub = &g_Upk[layer*22*8];
  ull r[16];

  // load in mapping M1: a = ((t>>4)<<8)|(v<<4)|(t&15), g = ((a>>2)<<12)|(blk<<2)|(a&3)
  const unsigned aM1b = (((unsigned)t>>4)<<8) | ((unsigned)t&15);
#pragma unroll
  for (int v=0;v<16;v++){
    unsigned a = aM1b | ((unsigned)v<<4);
    unsigned g = ((a>>2)<<12) | (blk<<2) | (a&3);
    r[v] = buf[g];
  }
  if (t < 80){
    const int qmap[10] = {7,6,5,4, 9,8, 3,2,1,0};
    shU[t] = Ub[qmap[t>>3]*8 + (t&7)];
  }
  __syncthreads();

  // stage M1: reg bit j -> a bit 4+j -> global bit 14+j -> qubit 7-j
  gate16<0>(r, shU + 0);
  gate16<1>(r, shU + 8);
  gate16<2>(r, shU + 16);
  gate16<3>(r, shU + 24);
  // exchange M1 -> M2
#pragma unroll
  for (int v=0;v<16;v++) sh[SWZ(aM1b | (v<<4))] = r[v];
  __syncthreads();
#pragma unroll
  for (int v=0;v<16;v++) r[v] = sh[SWZ((t<<4)|v)];
  // stage M2: reg bits 2,3 -> a bits 2,3 -> global 12,13 -> qubits 9,8
  gate16<2>(r, shU + 32);
  gate16<3>(r, shU + 40);
  // exchange M2 -> M0 (write back to just-read slots)
#pragma unroll
  for (int v=0;v<16;v++) sh[SWZ((t<<4)|v)] = r[v];
  __syncthreads();
#pragma unroll
  for (int v=0;v<16;v++) r[v] = sh[SWZ((v<<8)|t)];
  // stage M0: reg bit j -> a bit 8+j -> global bit 18+j -> qubit 3-j
  gate16<0>(r, shU + 48);
  gate16<1>(r, shU + 56);
  gate16<2>(r, shU + 64);
  gate16<3>(r, shU + 72);

  // M0 store: a=(v<<8)|t -> g = (v<<18)|((t>>2)<<12)|(blk<<2)|(t&3)
  const unsigned gbase0 = (((unsigned)t>>2)<<12) | (blk<<2) | ((unsigned)t&3);
#pragma unroll
  for (int v=0;v<16;v++) buf[gbase0 | ((unsigned)v<<18)] = r[v];
}

// ---------------------------------------------------------------------------
// Pass B (last): same gate structure, then fused final CNOT ladder + <Z_q>
// reduction (no final state store). Needs 22 accumulator regs -> 3 CTAs/SM.
// ---------------------------------------------------------------------------
__global__ void __launch_bounds__(256,3) k_passB_last(int layer, int sel)
{
  __shared__ ull sh[4096];
  __shared__ ull shU[80];
  __shared__ double sacc[23];
  const int t = threadIdx.x;
  const unsigned blk = blockIdx.x;
  ull* buf = sel ? g_bufA : g_bufB;
  const ull* Ub = &g_Upk[layer*22*8];
  ull r[16];

  const unsigned aM1b = (((unsigned)t>>4)<<8) | ((unsigned)t&15);
#pragma unroll
  for (int v=0;v<16;v++){
    unsigned a = aM1b | ((unsigned)v<<4);
    unsigned g = ((a>>2)<<12) | (blk<<2) | (a&3);
    r[v] = buf[g];
  }
  if (t < 80){
    const int qmap[10] = {7,6,5,4, 9,8, 3,2,1,0};
    shU[t] = Ub[qmap[t>>3]*8 + (t&7)];
  }
  if (t >= 128 && t < 151) sacc[t-128] = 0.0;
  __syncthreads();

  gate16<0>(r, shU + 0);
  gate16<1>(r, shU + 8);
  gate16<2>(r, shU + 16);
  gate16<3>(r, shU + 24);
#pragma unroll
  for (int v=0;v<16;v++) sh[SWZ(aM1b | (v<<4))] = r[v];
  __syncthreads();
#pragma unroll
  for (int v=0;v<16;v++) r[v] = sh[SWZ((t<<4)|v)];
  gate16<2>(r, shU + 32);
  gate16<3>(r, shU + 40);
#pragma unroll
  for (int v=0;v<16;v++) sh[SWZ((t<<4)|v)] = r[v];
  __syncthreads();
#pragma unroll
  for (int v=0;v<16;v++) r[v] = sh[SWZ((v<<8)|t)];
  gate16<0>(r, shU + 48);
  gate16<1>(r, shU + 56);
  gate16<2>(r, shU + 64);
  gate16<3>(r, shU + 72);

  // Fused final CNOT ladder + <Z_q> reduction.
  // r[v] lives at g = (v<<18)|((t>>2)<<12)|(blk<<2)|(t&3) (mapping M0);
  // post-ladder basis label y_p = XOR of g bits p..21 (prefix-xor).
  const unsigned gbase0 = (((unsigned)t>>2)<<12) | (blk<<2) | ((unsigned)t&3);
  float z[22];
#pragma unroll
  for (int q=0;q<22;q++) z[q] = 0.0f;
  float tot = 0.0f;
#pragma unroll
  for (int v=0;v<16;v++){
    unsigned g = gbase0 | ((unsigned)v<<18);
    unsigned y = g; y ^= y>>1; y ^= y>>2; y ^= y>>4; y ^= y>>8; y ^= y>>16;
    float re = __uint_as_float((unsigned)r[v]);
    float im = __uint_as_float((unsigned)(r[v]>>32));
    float p = re*re + im*im;
    tot += p;
#pragma unroll
    for (int q=0;q<22;q++)
      z[q] += ((y >> (21-q)) & 1u) ? -p : p;
  }
#pragma unroll
  for (int q=0;q<22;q++){
    float val = z[q];
#pragma unroll
    for (int o=16;o;o>>=1) val += __shfl_down_sync(0xffffffffu, val, o);
    if ((t & 31) == 0) atomicAdd(&sacc[q], (double)val);
  }
  {
    float val = tot;
#pragma unroll
    for (int o=16;o;o>>=1) val += __shfl_down_sync(0xffffffffu, val, o);
    if ((t & 31) == 0) atomicAdd(&sacc[22], (double)val);
  }
  __syncthreads();
  if (t < 23) atomicAdd(&g_acc[t], sacc[t]);
}

__global__ void k_final(float* __restrict__ out){
  int q = threadIdx.x;
  if (q < 22) out[q] = (float)(g_acc[q] / g_acc[22]);
}

extern "C" void kernel_launch(void* const* d_in, const int* in_sizes, int n_in,
                              void* d_out, int out_size)
{
  const float* params = (const float*)d_in[0];
  const float* sre    = (const float*)d_in[1];
  const float* sim    = (const float*)d_in[2];
  float* out = (float*)d_out;

  k_prep<<<1,128>>>(params);

  // Layer 1: A writes bufA (dir=1), B in-place on bufA (sel=1)
  k_passA<true ><<<1024,256>>>(sre, sim, 0, 1);
  k_passB<<<1024,256>>>(0, 1);
  // Layer 2: bufA -> bufB (dir=0), B on bufB (sel=0)
  k_passA<false><<<1024,256>>>(nullptr, nullptr, 1, 0);
  k_passB<<<1024,256>>>(1, 0);
  // Layer 3: bufB -> bufA
  k_passA<false><<<1024,256>>>(nullptr, nullptr, 2, 1);
  k_passB<<<1024,256>>>(2, 1);
  // Layer 4: bufA -> bufB, B fuses final ladder + reduction
  k_passA<false><<<1024,256>>>(nullptr, nullptr, 3, 0);
  k_passB_last<<<1024,256>>>(3, 0);

  k_final<<<1,32>>>(out);
}

// round 6
// speedup vs baseline: 1.0208x; 1.0208x over previous
#include <cuda_runtime.h>

#define DIM (1u<<22)
typedef unsigned long long ull;

// Persistent scratch (allowed: __device__ globals, no allocation)
__device__ ull g_bufA[DIM];                 // packed (re,im) amplitudes
__device__ ull g_bufB[DIM];
__device__ __align__(16) ull g_Upk[4*22*8]; // per gate: 8 packed-broadcast consts
__device__ double g_acc[23];                // z[0..21], total at [22]

__device__ __forceinline__ int SWZ(int a){ return a ^ ((a>>4)&15); }

__device__ __forceinline__ ull fma2(ull a, ull b, ull c){
  ull d; asm("fma.rn.f32x2 %0, %1, %2, %3;" : "=l"(d) : "l"(a), "l"(b), "l"(c)); return d;
}
__device__ __forceinline__ ull mul2(ull a, ull b){
  ull d; asm("mul.rn.f32x2 %0, %1, %2;" : "=l"(d) : "l"(a), "l"(b)); return d;
}
__device__ __forceinline__ ull swp(ull a){ return (a>>32)|(a<<32); }
__device__ __forceinline__ ull packf(float lo, float hi){
  return (ull)__float_as_uint(lo) | ((ull)__float_as_uint(hi)<<32);
}

__device__ __forceinline__ float2 cxmul(float2 a, float2 b){
  return make_float2(a.x*b.x - a.y*b.y, a.x*b.y + a.y*b.x);
}

// Apply 2x2 gate on register-bit J over 16 register-resident packed amps.
// Complex update via packed f32x2: res = (u.x,u.x)*a + (-u.y,u.y)*swap(a) + ...
template<int J>
__device__ __forceinline__ void gate16(ull (&r)[16], const ull* __restrict__ Up){
  const ulonglong2 q0 = ((const ulonglong2*)Up)[0];
  const ulonglong2 q1 = ((const ulonglong2*)Up)[1];
  const ulonglong2 q2 = ((const ulonglong2*)Up)[2];
  const ulonglong2 q3 = ((const ulonglong2*)Up)[3];
  const ull c00=q0.x, d00=q0.y, c01=q1.x, d01=q1.y;
  const ull c10=q2.x, d10=q2.y, c11=q3.x, d11=q3.y;
#pragma unroll
  for (int i=0;i<16;i++){
    if ((i & (1<<J)) == 0){
      const int j2 = i | (1<<J);
      const ull a=r[i], b=r[j2], as=swp(a), bs=swp(b);
      r[i]  = fma2(c00,a, fma2(d00,as, fma2(c01,b, mul2(d01,bs))));
      r[j2] = fma2(c10,a, fma2(d10,as, fma2(c11,b, mul2(d11,bs))));
    }
  }
}

// ---------------------------------------------------------------------------
// Prep: zero accumulators, build 88 fused gates U = RZ*RY*RX, packed-broadcast
// ---------------------------------------------------------------------------
__global__ void k_prep(const float* __restrict__ params){
  int i = threadIdx.x;
  if (i < 23) g_acc[i] = 0.0;
  if (i < 88){
    float tx = 0.5f*params[i*3+0];
    float ty = 0.5f*params[i*3+1];
    float tz = 0.5f*params[i*3+2];
    float cx,sx,cy,sy,cz,sz;
    sincosf(tx,&sx,&cx); sincosf(ty,&sy,&cy); sincosf(tz,&sz,&cz);
    // M = RY*RX
    float2 M00 = make_float2( cy*cx,  sy*sx);
    float2 M01 = make_float2(-sy*cx, -cy*sx);
    float2 M10 = make_float2( sy*cx, -cy*sx);
    float2 M11 = make_float2( cy*cx, -sy*sx);
    float2 em = make_float2(cz,-sz), ep = make_float2(cz,sz); // e^{-itz}, e^{+itz}
    float2 U00=cxmul(em,M00), U01=cxmul(em,M01);
    float2 U10=cxmul(ep,M10), U11=cxmul(ep,M11);
    ull* Up = &g_Upk[i*8];
    Up[0]=packf(U00.x,U00.x); Up[1]=packf(-U00.y,U00.y);
    Up[2]=packf(U01.x,U01.x); Up[3]=packf(-U01.y,U01.y);
    Up[4]=packf(U10.x,U10.x); Up[5]=packf(-U10.y,U10.y);
    Up[6]=packf(U11.x,U11.x); Up[7]=packf(-U11.y,U11.y);
  }
}

// ---------------------------------------------------------------------------
// Pass A (R4-winner config): gates on global bits 0..11 (qubits 21..10).
// Tile = 4096 contiguous. 2-exchange structure: load in M1 (coalesced),
// stages M1 -> M2 -> M0, store in M0 (coalesced). Stage M1 consts direct
// from global (no entry barrier); M2/M0 consts staged through smem.
// Layers >= 2 fuse prior layer's CNOT ladder as Gray-code gather in[y^(y>>1)].
//   M0: a=(v<<8)|t                  reg bits = a8..11
//   M1: a=((t>>4)<<8)|(v<<4)|(t&15) reg bits = a4..7
//   M2: a=(t<<4)|v                  reg bits = a0..3
// ---------------------------------------------------------------------------
template<bool FIRST>
__global__ void __launch_bounds__(256,3) k_passA(
    const float* __restrict__ sre, const float* __restrict__ sim,
    int layer, int dir)
{
  __shared__ ull sh[4096];
  __shared__ ull shU[64];               // M2 gates (q21..18), M0 gates (q13..10)
  const int t = threadIdx.x;
  const unsigned base = (unsigned)blockIdx.x << 12;
  const ull* in  = dir ? g_bufB : g_bufA;
  ull*       out = dir ? g_bufA : g_bufB;
  const ull* Ub = &g_Upk[layer*22*8];
  ull r[16];

  if (t < 64){
    const int qmap[8] = {21,20,19,18, 13,12,11,10};
    shU[t] = Ub[qmap[t>>3]*8 + (t&7)];
  }

  // load in mapping M1: a = ((t>>4)<<8)|(v<<4)|(t&15)
  const unsigned aM1b = (((unsigned)t>>4)<<8) | ((unsigned)t&15);
  if (FIRST){
#pragma unroll
    for (int v=0;v<16;v++){
      unsigned y = base | aM1b | ((unsigned)v<<4);
      r[v] = packf(sre[y], sim[y]);
    }
  } else {
#pragma unroll
    for (int v=0;v<16;v++){
      unsigned y = base | aM1b | ((unsigned)v<<4);
      unsigned x = y ^ (y>>1);          // inverse of CNOT-ladder permutation
      r[v] = in[x];
    }
  }
  // stage M1: reg bit j -> a bit 4+j -> qubit 17-j (consts direct from global)
  gate16<0>(r, Ub + 17*8);
  gate16<1>(r, Ub + 16*8);
  gate16<2>(r, Ub + 15*8);
  gate16<3>(r, Ub + 14*8);
  // exchange M1 -> M2
#pragma unroll
  for (int v=0;v<16;v++) sh[SWZ(aM1b | (v<<4))] = r[v];
  __syncthreads();
#pragma unroll
  for (int v=0;v<16;v++) r[v] = sh[SWZ((t<<4)|v)];
  // stage M2: reg bit j -> a bit j -> qubit 21-j (consts from smem)
  gate16<0>(r, shU + 0);
  gate16<1>(r, shU + 8);
  gate16<2>(r, shU + 16);
  gate16<3>(r, shU + 24);
  // exchange M2 -> M0 (write back to just-read slots: no pre-barrier needed)
#pragma unroll
  for (int v=0;v<16;v++) sh[SWZ((t<<4)|v)] = r[v];
  __syncthreads();
#pragma unroll
  for (int v=0;v<16;v++) r[v] = sh[SWZ((v<<8)|t)];
  // stage M0: reg bit j -> a bit 8+j -> qubit 13-j (consts from smem)
  gate16<0>(r, shU + 32);
  gate16<1>(r, shU + 40);
  gate16<2>(r, shU + 48);
  gate16<3>(r, shU + 56);
  // store in M0: coalesced
#pragma unroll
  for (int v=0;v<16;v++) out[base | ((unsigned)v<<8) | (unsigned)t] = r[v];
}

// ---------------------------------------------------------------------------
// Pass B (non-last, R5-winner config): gates on global bits 12..21
// (qubits 9..0). In-place. Tile local a (12b): a bits 0..1 = global bits 0..1
// (payload), a bit k (k>=2) = global bit 10+k.  g = ((a>>2)<<12)|(blk<<2)|(a&3).
// 2-exchange structure: load M1, stages M1 -> M2 -> M0, store M0.
// All consts staged through smem; 4 CTAs/SM.
// ---------------------------------------------------------------------------
__global__ void __launch_bounds__(256,4) k_passB(int layer, int sel)
{
  __shared__ ull sh[4096];
  __shared__ ull shU[80];   // M1 (q7..4), M2 (q9,q8), M0 (q3..0)
  const int t = threadIdx.x;
  const unsigned blk = blockIdx.x;
  ull* buf = sel ? g_bufA : g_bufB;
  const ull* Ub = &g_Upk[layer*22*8];
  ull r[16];

  // load in mapping M1: a = ((t>>4)<<8)|(v<<4)|(t&15), g = ((a>>2)<<12)|(blk<<2)|(a&3)
  const unsigned aM1b = (((unsigned)t>>4)<<8) | ((unsigned)t&15);
#pragma unroll
  for (int v=0;v<16;v++){
    unsigned a = aM1b | ((unsigned)v<<4);
    unsigned g = ((a>>2)<<12) | (blk<<2) | (a&3);
    r[v] = buf[g];
  }
  if (t < 80){
    const int qmap[10] = {7,6,5,4, 9,8, 3,2,1,0};
    shU[t] = Ub[qmap[t>>3]*8 + (t&7)];
  }
  __syncthreads();

  // stage M1: reg bit j -> a bit 4+j -> global bit 14+j -> qubit 7-j
  gate16<0>(r, shU + 0);
  gate16<1>(r, shU + 8);
  gate16<2>(r, shU + 16);
  gate16<3>(r, shU + 24);
  // exchange M1 -> M2
#pragma unroll
  for (int v=0;v<16;v++) sh[SWZ(aM1b | (v<<4))] = r[v];
  __syncthreads();
#pragma unroll
  for (int v=0;v<16;v++) r[v] = sh[SWZ((t<<4)|v)];
  // stage M2: reg bits 2,3 -> a bits 2,3 -> global 12,13 -> qubits 9,8
  gate16<2>(r, shU + 32);
  gate16<3>(r, shU + 40);
  // exchange M2 -> M0 (write back to just-read slots)
#pragma unroll
  for (int v=0;v<16;v++) sh[SWZ((t<<4)|v)] = r[v];
  __syncthreads();
#pragma unroll
  for (int v=0;v<16;v++) r[v] = sh[SWZ((v<<8)|t)];
  // stage M0: reg bit j -> a bit 8+j -> global bit 18+j -> qubit 3-j
  gate16<0>(r, shU + 48);
  gate16<1>(r, shU + 56);
  gate16<2>(r, shU + 64);
  gate16<3>(r, shU + 72);

  // M0 store: a=(v<<8)|t -> g = (v<<18)|((t>>2)<<12)|(blk<<2)|(t&3)
  const unsigned gbase0 = (((unsigned)t>>2)<<12) | (blk<<2) | ((unsigned)t&3);
#pragma unroll
  for (int v=0;v<16;v++) buf[gbase0 | ((unsigned)v<<18)] = r[v];
}

// ---------------------------------------------------------------------------
// Pass B (last): same gate structure, then fused final CNOT ladder + <Z_q>
// reduction (no final state store). Needs 22 accumulator regs -> 3 CTAs/SM.
// ---------------------------------------------------------------------------
__global__ void __launch_bounds__(256,3) k_passB_last(int layer, int sel)
{
  __shared__ ull sh[4096];
  __shared__ ull shU[80];
  __shared__ double sacc[23];
  const int t = threadIdx.x;
  const unsigned blk = blockIdx.x;
  ull* buf = sel ? g_bufA : g_bufB;
  const ull* Ub = &g_Upk[layer*22*8];
  ull r[16];

  const unsigned aM1b = (((unsigned)t>>4)<<8) | ((unsigned)t&15);
#pragma unroll
  for (int v=0;v<16;v++){
    unsigned a = aM1b | ((unsigned)v<<4);
    unsigned g = ((a>>2)<<12) | (blk<<2) | (a&3);
    r[v] = buf[g];
  }
  if (t < 80){
    const int qmap[10] = {7,6,5,4, 9,8, 3,2,1,0};
    shU[t] = Ub[qmap[t>>3]*8 + (t&7)];
  }
  if (t >= 128 && t < 151) sacc[t-128] = 0.0;
  __syncthreads();

  gate16<0>(r, shU + 0);
  gate16<1>(r, shU + 8);
  gate16<2>(r, shU + 16);
  gate16<3>(r, shU + 24);
#pragma unroll
  for (int v=0;v<16;v++) sh[SWZ(aM1b | (v<<4))] = r[v];
  __syncthreads();
#pragma unroll
  for (int v=0;v<16;v++) r[v] = sh[SWZ((t<<4)|v)];
  gate16<2>(r, shU + 32);
  gate16<3>(r, shU + 40);
#pragma unroll
  for (int v=0;v<16;v++) sh[SWZ((t<<4)|v)] = r[v];
  __syncthreads();
#pragma unroll
  for (int v=0;v<16;v++) r[v] = sh[SWZ((v<<8)|t)];
  gate16<0>(r, shU + 48);
  gate16<1>(r, shU + 56);
  gate16<2>(r, shU + 64);
  gate16<3>(r, shU + 72);

  // Fused final CNOT ladder + <Z_q> reduction.
  // r[v] lives at g = (v<<18)|((t>>2)<<12)|(blk<<2)|(t&3) (mapping M0);
  // post-ladder basis label y_p = XOR of g bits p..21 (prefix-xor).
  const unsigned gbase0 = (((unsigned)t>>2)<<12) | (blk<<2) | ((unsigned)t&3);
  float z[22];
#pragma unroll
  for (int q=0;q<22;q++) z[q] = 0.0f;
  float tot = 0.0f;
#pragma unroll
  for (int v=0;v<16;v++){
    unsigned g = gbase0 | ((unsigned)v<<18);
    unsigned y = g; y ^= y>>1; y ^= y>>2; y ^= y>>4; y ^= y>>8; y ^= y>>16;
    float re = __uint_as_float((unsigned)r[v]);
    float im = __uint_as_float((unsigned)(r[v]>>32));
    float p = re*re + im*im;
    tot += p;
#pragma unroll
    for (int q=0;q<22;q++)
      z[q] += ((y >> (21-q)) & 1u) ? -p : p;
  }
#pragma unroll
  for (int q=0;q<22;q++){
    float val = z[q];
#pragma unroll
    for (int o=16;o;o>>=1) val += __shfl_down_sync(0xffffffffu, val, o);
    if ((t & 31) == 0) atomicAdd(&sacc[q], (double)val);
  }
  {
    float val = tot;
#pragma unroll
    for (int o=16;o;o>>=1) val += __shfl_down_sync(0xffffffffu, val, o);
    if ((t & 31) == 0) atomicAdd(&sacc[22], (double)val);
  }
  __syncthreads();
  if (t < 23) atomicAdd(&g_acc[t], sacc[t]);
}

__global__ void k_final(float* __restrict__ out){
  int q = threadIdx.x;
  if (q < 22) out[q] = (float)(g_acc[q] / g_acc[22]);
}

extern "C" void kernel_launch(void* const* d_in, const int* in_sizes, int n_in,
                              void* d_out, int out_size)
{
  const float* params = (const float*)d_in[0];
  const float* sre    = (const float*)d_in[1];
  const float* sim    = (const float*)d_in[2];
  float* out = (float*)d_out;

  k_prep<<<1,128>>>(params);

  // Layer 1: A writes bufA (dir=1), B in-place on bufA (sel=1)
  k_passA<true ><<<1024,256>>>(sre, sim, 0, 1);
  k_passB<<<1024,256>>>(0, 1);
  // Layer 2: bufA -> bufB (dir=0), B on bufB (sel=0)
  k_passA<false><<<1024,256>>>(nullptr, nullptr, 1, 0);
  k_passB<<<1024,256>>>(1, 0);
  // Layer 3: bufB -> bufA
  k_passA<false><<<1024,256>>>(nullptr, nullptr, 2, 1);
  k_passB<<<1024,256>>>(2, 1);
  // Layer 4: bufA -> bufB, B fuses final ladder + reduction
  k_passA<false><<<1024,256>>>(nullptr, nullptr, 3, 0);
  k_passB_last<<<1024,256>>>(3, 0);

  k_final<<<1,32>>>(out);
}

// round 7
// speedup vs baseline: 1.0224x; 1.0016x over previous
#include <cuda_runtime.h>

#define DIM (1u<<22)
typedef unsigned long long ull;

// Persistent scratch (allowed: __device__ globals, no allocation)
__device__ ull g_bufA[DIM];                 // packed (re,im) amplitudes
__device__ ull g_bufB[DIM];
__device__ __align__(16) ull g_Upk[4*22*8]; // per gate: 8 packed-broadcast consts
__device__ double g_acc[23];                // z[0..21], total at [22]

__device__ __forceinline__ int SWZ(int a){ return a ^ ((a>>4)&15); }

__device__ __forceinline__ ull fma2(ull a, ull b, ull c){
  ull d; asm("fma.rn.f32x2 %0, %1, %2, %3;" : "=l"(d) : "l"(a), "l"(b), "l"(c)); return d;
}
__device__ __forceinline__ ull mul2(ull a, ull b){
  ull d; asm("mul.rn.f32x2 %0, %1, %2;" : "=l"(d) : "l"(a), "l"(b)); return d;
}
__device__ __forceinline__ ull swp(ull a){ return (a>>32)|(a<<32); }
__device__ __forceinline__ ull packf(float lo, float hi){
  return (ull)__float_as_uint(lo) | ((ull)__float_as_uint(hi)<<32);
}

__device__ __forceinline__ float2 cxmul(float2 a, float2 b){
  return make_float2(a.x*b.x - a.y*b.y, a.x*b.y + a.y*b.x);
}

// Apply 2x2 gate on register-bit J over 16 register-resident packed amps.
// Complex update via packed f32x2: res = (u.x,u.x)*a + (-u.y,u.y)*swap(a) + ...
template<int J>
__device__ __forceinline__ void gate16(ull (&r)[16], const ull* __restrict__ Up){
  const ulonglong2 q0 = ((const ulonglong2*)Up)[0];
  const ulonglong2 q1 = ((const ulonglong2*)Up)[1];
  const ulonglong2 q2 = ((const ulonglong2*)Up)[2];
  const ulonglong2 q3 = ((const ulonglong2*)Up)[3];
  const ull c00=q0.x, d00=q0.y, c01=q1.x, d01=q1.y;
  const ull c10=q2.x, d10=q2.y, c11=q3.x, d11=q3.y;
#pragma unroll
  for (int i=0;i<16;i++){
    if ((i & (1<<J)) == 0){
      const int j2 = i | (1<<J);
      const ull a=r[i], b=r[j2], as=swp(a), bs=swp(b);
      r[i]  = fma2(c00,a, fma2(d00,as, fma2(c01,b, mul2(d01,bs))));
      r[j2] = fma2(c10,a, fma2(d10,as, fma2(c11,b, mul2(d11,bs))));
    }
  }
}

// ---------------------------------------------------------------------------
// Prep: zero accumulators, build 88 fused gates U = RZ*RY*RX, packed-broadcast
// ---------------------------------------------------------------------------
__global__ void k_prep(const float* __restrict__ params){
  int i = threadIdx.x;
  if (i < 23) g_acc[i] = 0.0;
  if (i < 88){
    float tx = 0.5f*params[i*3+0];
    float ty = 0.5f*params[i*3+1];
    float tz = 0.5f*params[i*3+2];
    float cx,sx,cy,sy,cz,sz;
    sincosf(tx,&sx,&cx); sincosf(ty,&sy,&cy); sincosf(tz,&sz,&cz);
    // M = RY*RX
    float2 M00 = make_float2( cy*cx,  sy*sx);
    float2 M01 = make_float2(-sy*cx, -cy*sx);
    float2 M10 = make_float2( sy*cx, -cy*sx);
    float2 M11 = make_float2( cy*cx, -sy*sx);
    float2 em = make_float2(cz,-sz), ep = make_float2(cz,sz); // e^{-itz}, e^{+itz}
    float2 U00=cxmul(em,M00), U01=cxmul(em,M01);
    float2 U10=cxmul(ep,M10), U11=cxmul(ep,M11);
    ull* Up = &g_Upk[i*8];
    Up[0]=packf(U00.x,U00.x); Up[1]=packf(-U00.y,U00.y);
    Up[2]=packf(U01.x,U01.x); Up[3]=packf(-U01.y,U01.y);
    Up[4]=packf(U10.x,U10.x); Up[5]=packf(-U10.y,U10.y);
    Up[6]=packf(U11.x,U11.x); Up[7]=packf(-U11.y,U11.y);
  }
}

// ---------------------------------------------------------------------------
// Pass A: gates on global bits 0..11 (qubits 21..10). Tile = 4096 contiguous.
// 2-exchange structure; exchange M1->M2 is 16-thread (half-warp) local:
// amp bits 8..11 sit at t>>4 in BOTH mappings -> __syncwarp suffices.
// Only exchange M2->M0 needs a full block barrier (1 per pass).
// Consts: M1 direct from global; M2/M0 from smem, staged PER WARP with
// duplicated identical writes (benign) so no block barrier is needed.
//   M0: a=(v<<8)|t                  reg bits = a8..11
//   M1: a=((t>>4)<<8)|(v<<4)|(t&15) reg bits = a4..7
//   M2: a=(t<<4)|v                  reg bits = a0..3
// Layers >= 2 fuse prior layer's CNOT ladder as Gray-code gather in[y^(y>>1)].
// ---------------------------------------------------------------------------
template<bool FIRST>
__global__ void __launch_bounds__(256,3) k_passA(
    const float* __restrict__ sre, const float* __restrict__ sim,
    int layer, int dir)
{
  __shared__ ull sh[4096];
  __shared__ ull shU[64];               // M2 gates (q21..18), M0 gates (q13..10)
  const int t = threadIdx.x;
  const unsigned base = (unsigned)blockIdx.x << 12;
  const ull* in  = dir ? g_bufB : g_bufA;
  ull*       out = dir ? g_bufA : g_bufB;
  const ull* Ub = &g_Upk[layer*22*8];
  ull r[16];

  // amp loads first (max LDG overlap)
  const unsigned aM1b = (((unsigned)t>>4)<<8) | ((unsigned)t&15);
  if (FIRST){
#pragma unroll
    for (int v=0;v<16;v++){
      unsigned y = base | aM1b | ((unsigned)v<<4);
      r[v] = packf(sre[y], sim[y]);
    }
  } else {
#pragma unroll
    for (int v=0;v<16;v++){
      unsigned y = base | aM1b | ((unsigned)v<<4);
      unsigned x = y ^ (y>>1);          // inverse of CNOT-ladder permutation
      r[v] = in[x];
    }
  }
  // per-warp duplicated const staging: every warp writes identical values
  {
    const int l = (t & 31) * 2;
    const int qmapA[8] = {21,20,19,18, 13,12,11,10};
    shU[l]   = Ub[qmapA[l>>3]*8 + (l&7)];
    shU[l+1] = Ub[qmapA[(l+1)>>3]*8 + ((l+1)&7)];
  }

  // stage M1: reg bit j -> a bit 4+j -> qubit 17-j (consts direct from global)
  gate16<0>(r, Ub + 17*8);
  gate16<1>(r, Ub + 16*8);
  gate16<2>(r, Ub + 15*8);
  gate16<3>(r, Ub + 14*8);
  // exchange M1 -> M2: half-warp local (amp bits 8..11 fixed at t>>4)
#pragma unroll
  for (int v=0;v<16;v++) sh[SWZ(aM1b | (v<<4))] = r[v];
  __syncwarp();
#pragma unroll
  for (int v=0;v<16;v++) r[v] = sh[SWZ((t<<4)|v)];
  // stage M2: reg bit j -> a bit j -> qubit 21-j (smem consts; this warp
  // wrote shU and the syncwarp above ordered them)
  gate16<0>(r, shU + 0);
  gate16<1>(r, shU + 8);
  gate16<2>(r, shU + 16);
  gate16<3>(r, shU + 24);
  // exchange M2 -> M0: block-wide (the single full barrier of the pass)
#pragma unroll
  for (int v=0;v<16;v++) sh[SWZ((t<<4)|v)] = r[v];
  __syncthreads();
#pragma unroll
  for (int v=0;v<16;v++) r[v] = sh[SWZ((v<<8)|t)];
  // stage M0: reg bit j -> a bit 8+j -> qubit 13-j (smem consts)
  gate16<0>(r, shU + 32);
  gate16<1>(r, shU + 40);
  gate16<2>(r, shU + 48);
  gate16<3>(r, shU + 56);
  // store in M0: coalesced
#pragma unroll
  for (int v=0;v<16;v++) out[base | ((unsigned)v<<8) | (unsigned)t] = r[v];
}

// ---------------------------------------------------------------------------
// Pass B (non-last): gates on global bits 12..21 (qubits 9..0). In-place.
// Tile local a (12b): a bits 0..1 = global bits 0..1 (payload),
// a bit k (k>=2) = global bit 10+k.  g = ((a>>2)<<12)|(blk<<2)|(a&3).
// Same barrier structure as pass A: per-warp const staging + syncwarp,
// local exchange M1->M2 (syncwarp), one full barrier at M2->M0.
// ---------------------------------------------------------------------------
__global__ void __launch_bounds__(256,4) k_passB(int layer, int sel)
{
  __shared__ ull sh[4096];
  __shared__ ull shU[80];   // M1 (q7..4), M2 (q9,q8), M0 (q3..0)
  const int t = threadIdx.x;
  const unsigned blk = blockIdx.x;
  ull* buf = sel ? g_bufA : g_bufB;
  const ull* Ub = &g_Upk[layer*22*8];
  ull r[16];

  // amp loads first: a = ((t>>4)<<8)|(v<<4)|(t&15), g = ((a>>2)<<12)|(blk<<2)|(a&3)
  const unsigned aM1b = (((unsigned)t>>4)<<8) | ((unsigned)t&15);
#pragma unroll
  for (int v=0;v<16;v++){
    unsigned a = aM1b | ((unsigned)v<<4);
    unsigned g = ((a>>2)<<12) | (blk<<2) | (a&3);
    r[v] = buf[g];
  }
  // per-warp duplicated const staging (identical writes, benign races)
  {
    const int l = (t & 31) * 3;
    const int qmapB[10] = {7,6,5,4, 9,8, 3,2,1,0};
    if (l   < 80) shU[l]   = Ub[qmapB[l>>3]*8 + (l&7)];
    if (l+1 < 80) shU[l+1] = Ub[qmapB[(l+1)>>3]*8 + ((l+1)&7)];
    if (l+2 < 80) shU[l+2] = Ub[qmapB[(l+2)>>3]*8 + ((l+2)&7)];
  }
  __syncwarp();   // consts visible warp-wide before stage M1

  // stage M1: reg bit j -> a bit 4+j -> global bit 14+j -> qubit 7-j
  gate16<0>(r, shU + 0);
  gate16<1>(r, shU + 8);
  gate16<2>(r, shU + 16);
  gate16<3>(r, shU + 24);
  // exchange M1 -> M2: half-warp local
#pragma unroll
  for (int v=0;v<16;v++) sh[SWZ(aM1b | (v<<4))] = r[v];
  __syncwarp();
#pragma unroll
  for (int v=0;v<16;v++) r[v] = sh[SWZ((t<<4)|v)];
  // stage M2: reg bits 2,3 -> a bits 2,3 -> global 12,13 -> qubits 9,8
  gate16<2>(r, shU + 32);
  gate16<3>(r, shU + 40);
  // exchange M2 -> M0: block-wide (single full barrier)
#pragma unroll
  for (int v=0;v<16;v++) sh[SWZ((t<<4)|v)] = r[v];
  __syncthreads();
#pragma unroll
  for (int v=0;v<16;v++) r[v] = sh[SWZ((v<<8)|t)];
  // stage M0: reg bit j -> a bit 8+j -> global bit 18+j -> qubit 3-j
  gate16<0>(r, shU + 48);
  gate16<1>(r, shU + 56);
  gate16<2>(r, shU + 64);
  gate16<3>(r, shU + 72);

  // M0 store: a=(v<<8)|t -> g = (v<<18)|((t>>2)<<12)|(blk<<2)|(t&3)
  const unsigned gbase0 = (((unsigned)t>>2)<<12) | (blk<<2) | ((unsigned)t&3);
#pragma unroll
  for (int v=0;v<16;v++) buf[gbase0 | ((unsigned)v<<18)] = r[v];
}

// ---------------------------------------------------------------------------
// Pass B (last): same gate structure, then fused final CNOT ladder + <Z_q>
// reduction (no final state store). Needs 22 accumulator regs -> 3 CTAs/SM.
// ---------------------------------------------------------------------------
__global__ void __launch_bounds__(256,3) k_passB_last(int layer, int sel)
{
  __shared__ ull sh[4096];
  __shared__ ull shU[80];
  __shared__ double sacc[23];
  const int t = threadIdx.x;
  const unsigned blk = blockIdx.x;
  ull* buf = sel ? g_bufA : g_bufB;
  const ull* Ub = &g_Upk[layer*22*8];
  ull r[16];

  const unsigned aM1b = (((unsigned)t>>4)<<8) | ((unsigned)t&15);
#pragma unroll
  for (int v=0;v<16;v++){
    unsigned a = aM1b | ((unsigned)v<<4);
    unsigned g = ((a>>2)<<12) | (blk<<2) | (a&3);
    r[v] = buf[g];
  }
  {
    const int l = (t & 31) * 3;
    const int qmapB[10] = {7,6,5,4, 9,8, 3,2,1,0};
    if (l   < 80) shU[l]   = Ub[qmapB[l>>3]*8 + (l&7)];
    if (l+1 < 80) shU[l+1] = Ub[qmapB[(l+1)>>3]*8 + ((l+1)&7)];
    if (l+2 < 80) shU[l+2] = Ub[qmapB[(l+2)>>3]*8 + ((l+2)&7)];
  }
  if (t < 23) sacc[t] = 0.0;   // ordered before use by the M2->M0 syncthreads
  __syncwarp();

  gate16<0>(r, shU + 0);
  gate16<1>(r, shU + 8);
  gate16<2>(r, shU + 16);
  gate16<3>(r, shU + 24);
#pragma unroll
  for (int v=0;v<16;v++) sh[SWZ(aM1b | (v<<4))] = r[v];
  __syncwarp();
#pragma unroll
  for (int v=0;v<16;v++) r[v] = sh[SWZ((t<<4)|v)];
  gate16<2>(r, shU + 32);
  gate16<3>(r, shU + 40);
#pragma unroll
  for (int v=0;v<16;v++) sh[SWZ((t<<4)|v)] = r[v];
  __syncthreads();
#pragma unroll
  for (int v=0;v<16;v++) r[v] = sh[SWZ((v<<8)|t)];
  gate16<0>(r, shU + 48);
  gate16<1>(r, shU + 56);
  gate16<2>(r, shU + 64);
  gate16<3>(r, shU + 72);

  // Fused final CNOT ladder + <Z_q> reduction.
  // r[v] lives at g = (v<<18)|((t>>2)<<12)|(blk<<2)|(t&3) (mapping M0);
  // post-ladder basis label y_p = XOR of g bits p..21 (prefix-xor).
  const unsigned gbase0 = (((unsigned)t>>2)<<12) | (blk<<2) | ((unsigned)t&3);
  float z[22];
#pragma unroll
  for (int q=0;q<22;q++) z[q] = 0.0f;
  float tot = 0.0f;
#pragma unroll
  for (int v=0;v<16;v++){
    unsigned g = gbase0 | ((unsigned)v<<18);
    unsigned y = g; y ^= y>>1; y ^= y>>2; y ^= y>>4; y ^= y>>8; y ^= y>>16;
    float re = __uint_as_float((unsigned)r[v]);
    float im = __uint_as_float((unsigned)(r[v]>>32));
    float p = re*re + im*im;
    tot += p;
#pragma unroll
    for (int q=0;q<22;q++)
      z[q] += ((y >> (21-q)) & 1u) ? -p : p;
  }
#pragma unroll
  for (int q=0;q<22;q++){
    float val = z[q];
#pragma unroll
    for (int o=16;o;o>>=1) val += __shfl_down_sync(0xffffffffu, val, o);
    if ((t & 31) == 0) atomicAdd(&sacc[q], (double)val);
  }
  {
    float val = tot;
#pragma unroll
    for (int o=16;o;o>>=1) val += __shfl_down_sync(0xffffffffu, val, o);
    if ((t & 31) == 0) atomicAdd(&sacc[22], (double)val);
  }
  __syncthreads();
  if (t < 23) atomicAdd(&g_acc[t], sacc[t]);
}

__global__ void k_final(float* __restrict__ out){
  int q = threadIdx.x;
  if (q < 22) out[q] = (float)(g_acc[q] / g_acc[22]);
}

extern "C" void kernel_launch(void* const* d_in, const int* in_sizes, int n_in,
                              void* d_out, int out_size)
{
  const float* params = (const float*)d_in[0];
  const float* sre    = (const float*)d_in[1];
  const float* sim    = (const float*)d_in[2];
  float* out = (float*)d_out;

  k_prep<<<1,128>>>(params);

  // Layer 1: A writes bufA (dir=1), B in-place on bufA (sel=1)
  k_passA<true ><<<1024,256>>>(sre, sim, 0, 1);
  k_passB<<<1024,256>>>(0, 1);
  // Layer 2: bufA -> bufB (dir=0), B on bufB (sel=0)
  k_passA<false><<<1024,256>>>(nullptr, nullptr, 1, 0);
  k_passB<<<1024,256>>>(1, 0);
  // Layer 3: bufB -> bufA
  k_passA<false><<<1024,256>>>(nullptr, nullptr, 2, 1);
  k_passB<<<1024,256>>>(2, 1);
  // Layer 4: bufA -> bufB, B fuses final ladder + reduction
  k_passA<false><<<1024,256>>>(nullptr, nullptr, 3, 0);
  k_passB_last<<<1024,256>>>(3, 0);

  k_final<<<1,32>>>(out);
}